// round 13
// baseline (speedup 1.0000x reference)
#include <cuda_runtime.h>
#include <cuda_fp16.h>
#include <cstdint>

#define OUTF 2048
#define INF  2048
#define SWARM 32
#define MROWS (4*4096)

#define NCHUNK 4
#define KCH (INF / NCHUNK)    // 512 K-columns per chunk

// Device-global scratch (no runtime allocation allowed)
__device__ __half g_W[(size_t)OUTF * INF];   // 8 MB: sign weights, +/-1 in fp16
__device__ __half g_X[(size_t)MROWS * INF];  // 64 MB: x converted to fp16

// ---------------------------------------------------------------------------
// Kernel 1: swarm reduction for K-columns [k0, k0+KCH).
// 8 threads per (n,k) row x 4 rows per thread (coalesced 128B lines, MLP=4).
// ---------------------------------------------------------------------------
__global__ void pop_chunk_kernel(const float* __restrict__ pop, int k0) {
    int gt  = blockIdx.x * blockDim.x + threadIdx.x;
    int c   = gt & 7;                 // float4 chunk within 32-float row
    int r4  = (gt >> 3) * 4;          // local row base within chunk (mult of 4)
    int n   = r4 >> 9;                // KCH=512 local rows per n
    int kk  = r4 & (KCH - 1);
    size_t grow = (size_t)n * INF + k0 + kk;   // global (n,k) flat row
    const float4* p = reinterpret_cast<const float4*>(pop);

    float4 v0 = p[(grow + 0) * 8 + c];
    float4 v1 = p[(grow + 1) * 8 + c];
    float4 v2 = p[(grow + 2) * 8 + c];
    float4 v3 = p[(grow + 3) * 8 + c];

    float s0 = (v0.x + v0.y) + (v0.z + v0.w);
    float s1 = (v1.x + v1.y) + (v1.z + v1.w);
    float s2 = (v2.x + v2.y) + (v2.z + v2.w);
    float s3 = (v3.x + v3.y) + (v3.z + v3.w);
#pragma unroll
    for (int d = 1; d <= 4; d <<= 1) {
        s0 += __shfl_xor_sync(0xFFFFFFFFu, s0, d);
        s1 += __shfl_xor_sync(0xFFFFFFFFu, s1, d);
        s2 += __shfl_xor_sync(0xFFFFFFFFu, s2, d);
        s3 += __shfl_xor_sync(0xFFFFFFFFu, s3, d);
    }
    if (c == 0) {
        g_W[grow + 0] = __float2half(s0 >= 0.f ? 1.f : -1.f);
        g_W[grow + 1] = __float2half(s1 >= 0.f ? 1.f : -1.f);
        g_W[grow + 2] = __float2half(s2 >= 0.f ? 1.f : -1.f);
        g_W[grow + 3] = __float2half(s3 >= 0.f ? 1.f : -1.f);
    }
}

// ---------------------------------------------------------------------------
// Kernel 2: x fp32 -> fp16 for K-columns [k0, k0+KCH). 8 floats per thread.
// ---------------------------------------------------------------------------
__global__ void conv_chunk_kernel(const float* __restrict__ x, int k0) {
    int gt = blockIdx.x * blockDim.x + threadIdx.x;
    int m  = gt >> 6;                 // 64 threads per row-chunk (512 floats)
    int j  = gt & 63;
    size_t off = (size_t)m * INF + k0 + j * 8;     // element offset
    const float4* px = reinterpret_cast<const float4*>(x + off);
    float4 v0 = px[0];
    float4 v1 = px[1];
    __half2* o = reinterpret_cast<__half2*>(g_X + off);
    o[0] = __floats2half2_rn(v0.x, v0.y);
    o[1] = __floats2half2_rn(v0.z, v0.w);
    o[2] = __floats2half2_rn(v1.x, v1.y);
    o[3] = __floats2half2_rn(v1.z, v1.w);
}

// ---------------------------------------------------------------------------
// Kernel 3: GEMM over one K-chunk:  C (+)= X[:,k0:k0+KCH] * W[:,k0:k0+KCH]^T
// mma.sync.m16n8k16 + ldmatrix.x4 + 3-stage cp.async pipeline (R12-proven).
// ---------------------------------------------------------------------------
#define BM 128
#define BN 128
#define BK 32
#define STAGE 16384        // A 8KB + B 8KB
#define NSTAGE 3
#define KT (KCH / BK)      // 16 tiles per chunk

__device__ __forceinline__ uint32_t smem_u32(const void* p) {
    uint32_t a;
    asm("{ .reg .u64 t; cvta.to.shared.u64 t, %1; cvt.u32.u64 %0, t; }"
        : "=r"(a) : "l"(p));
    return a;
}

__device__ __forceinline__ void ldsm_x4(uint32_t* r, uint32_t addr) {
    asm volatile("ldmatrix.sync.aligned.m8n8.x4.shared.b16 {%0,%1,%2,%3}, [%4];"
                 : "=r"(r[0]), "=r"(r[1]), "=r"(r[2]), "=r"(r[3]) : "r"(addr));
}

__global__ __launch_bounds__(256, 2)
void gemm_hmma_kernel(float* __restrict__ C, int k0, int beta) {
    __shared__ __align__(1024) char smem[NSTAGE * STAGE];
    const uint32_t sbase = smem_u32(smem);

    const int tid  = threadIdx.x;
    const int warp = tid >> 5;
    const int lane = tid & 31;
    const int warpM = warp & 3;
    const int warpN = warp >> 2;
    const int g   = lane >> 2;
    const int tig = lane & 3;
    const int r8  = lane & 7;
    const int mh  = (lane >> 3) & 1;
    const int mk  = lane >> 4;

    const int blockM = blockIdx.y * BM;   // grid.x = N-blocks (fastest): L2 A reuse
    const int blockN = blockIdx.x * BN;

    float acc[2][8][4];
#pragma unroll
    for (int mi = 0; mi < 2; mi++)
#pragma unroll
        for (int ni = 0; ni < 8; ni++)
#pragma unroll
            for (int r = 0; r < 4; r++) acc[mi][ni][r] = 0.f;

    auto fill = [&](int c) {
        const int s = c % NSTAGE;
        const uint32_t ab = sbase + s * STAGE;
        const uint32_t bb = ab + 8192;
        const int kt0 = k0 + c * BK;
#pragma unroll
        for (int t = 0; t < 2; t++) {
            int id  = t * 256 + tid;
            int row = id >> 2, ch = id & 3;
            uint32_t da = ab + row * 64 + ((ch ^ (row & 3)) << 4);
            const void* sa = g_X + (size_t)(blockM + row) * INF + kt0 + ch * 8;
            asm volatile("cp.async.cg.shared.global [%0], [%1], 16;" :: "r"(da), "l"(sa));
            uint32_t db = bb + row * 64 + ((ch ^ (row & 3)) << 4);
            const void* sb = g_W + (size_t)(blockN + row) * INF + kt0 + ch * 8;
            asm volatile("cp.async.cg.shared.global [%0], [%1], 16;" :: "r"(db), "l"(sb));
        }
        asm volatile("cp.async.commit_group;");
    };

    fill(0);
    fill(1);

    for (int c = 0; c < KT; c++) {
        if (c + 1 < KT) asm volatile("cp.async.wait_group 1;");
        else            asm volatile("cp.async.wait_group 0;");
        __syncthreads();
        if (c + 2 < KT) fill(c + 2);

        const uint32_t ab = sbase + (c % NSTAGE) * STAGE;
        const uint32_t bb = ab + 8192;

#pragma unroll
        for (int ks = 0; ks < 2; ks++) {
            uint32_t a[2][4], b[4][4];
#pragma unroll
            for (int mi = 0; mi < 2; mi++) {
                int row = warpM * 32 + mi * 16 + mh * 8 + r8;
                int ch  = ks * 2 + mk;
                ldsm_x4(a[mi], ab + row * 64 + ((ch ^ (row & 3)) << 4));
            }
#pragma unroll
            for (int p = 0; p < 4; p++) {
                int row = warpN * 64 + p * 16 + mk * 8 + r8;
                int ch  = ks * 2 + mh;
                ldsm_x4(b[p], bb + row * 64 + ((ch ^ (row & 3)) << 4));
            }
#pragma unroll
            for (int mi = 0; mi < 2; mi++)
#pragma unroll
                for (int ni = 0; ni < 8; ni++) {
                    const uint32_t b0 = b[ni >> 1][(ni & 1) * 2];
                    const uint32_t b1 = b[ni >> 1][(ni & 1) * 2 + 1];
                    asm volatile(
                        "mma.sync.aligned.m16n8k16.row.col.f32.f16.f16.f32 "
                        "{%0,%1,%2,%3}, {%4,%5,%6,%7}, {%8,%9}, {%0,%1,%2,%3};"
                        : "+f"(acc[mi][ni][0]), "+f"(acc[mi][ni][1]),
                          "+f"(acc[mi][ni][2]), "+f"(acc[mi][ni][3])
                        : "r"(a[mi][0]), "r"(a[mi][1]), "r"(a[mi][2]), "r"(a[mi][3]),
                          "r"(b0), "r"(b1));
                }
        }
    }

    // epilogue: write or accumulate
#pragma unroll
    for (int mi = 0; mi < 2; mi++) {
        int row0 = blockM + warpM * 32 + mi * 16 + g;
#pragma unroll
        for (int ni = 0; ni < 8; ni++) {
            int col = blockN + warpN * 64 + ni * 8 + tig * 2;
            float2* p0 = reinterpret_cast<float2*>(C + (size_t)row0 * OUTF + col);
            float2* p1 = reinterpret_cast<float2*>(C + (size_t)(row0 + 8) * OUTF + col);
            float2 v0 = make_float2(acc[mi][ni][0], acc[mi][ni][1]);
            float2 v1 = make_float2(acc[mi][ni][2], acc[mi][ni][3]);
            if (beta) {
                float2 o0 = *p0, o1 = *p1;
                v0.x += o0.x; v0.y += o0.y;
                v1.x += o1.x; v1.y += o1.y;
            }
            *p0 = v0;
            *p1 = v1;
        }
    }
}

// ---------------------------------------------------------------------------
// Launch: chunk-0 production serial, chunks 1..3 produced on a forked stream
// concurrently with the GEMM on earlier chunks (event fork/join — the
// canonical graph-capture pattern; kernel launches + event edges only).
// ---------------------------------------------------------------------------
extern "C" void kernel_launch(void* const* d_in, const int* in_sizes, int n_in,
                              void* d_out, int out_size) {
    const float* x   = (const float*)d_in[0];
    const float* pop = (const float*)d_in[1];
    if (n_in >= 2 && in_sizes[0] == OUTF * INF * SWARM) {
        pop = (const float*)d_in[0];
        x   = (const float*)d_in[1];
    }
    float* out = (float*)d_out;

    const int POP_BLOCKS  = (OUTF * KCH / 4 * 8) / 256;   // 8192
    const int CONV_BLOCKS = (MROWS * KCH / 8) / 256;      // 4096
    dim3 gemm_grid(OUTF / BN, MROWS / BM);                // (16, 128), N fastest

    cudaStream_t s1;
    cudaEvent_t evFork, evC[NCHUNK];
    bool forked = (cudaStreamCreateWithFlags(&s1, cudaStreamNonBlocking) == cudaSuccess);
    if (forked) {
        forked &= (cudaEventCreateWithFlags(&evFork, cudaEventDisableTiming) == cudaSuccess);
        for (int c = 1; c < NCHUNK && forked; c++)
            forked &= (cudaEventCreateWithFlags(&evC[c], cudaEventDisableTiming) == cudaSuccess);
    }

    if (forked) {
        // chunk 0 production on the origin stream
        pop_chunk_kernel<<<POP_BLOCKS, 256>>>(pop, 0);
        conv_chunk_kernel<<<CONV_BLOCKS, 256>>>(x, 0);
        cudaEventRecord(evFork, 0);
        cudaStreamWaitEvent(s1, evFork, 0);
        // chunks 1..3 production on the forked stream
        for (int c = 1; c < NCHUNK; c++) {
            pop_chunk_kernel<<<POP_BLOCKS, 256, 0, s1>>>(pop, c * KCH);
            conv_chunk_kernel<<<CONV_BLOCKS, 256, 0, s1>>>(x, c * KCH);
            cudaEventRecord(evC[c], s1);
        }
        // GEMM chain on the origin stream, joining each chunk as it's needed
        gemm_hmma_kernel<<<gemm_grid, 256>>>(out, 0, 0);
        for (int c = 1; c < NCHUNK; c++) {
            cudaStreamWaitEvent(0, evC[c], 0);
            gemm_hmma_kernel<<<gemm_grid, 256>>>(out, c * KCH, 1);
        }
        // intentionally not destroyed: kernel_launch is called O(1) times
        // (replays are graph replays); destroying forked streams mid-capture
        // is the riskier operation.
    } else {
        // serial fallback: identical math
        for (int c = 0; c < NCHUNK; c++) {
            pop_chunk_kernel<<<POP_BLOCKS, 256>>>(pop, c * KCH);
            conv_chunk_kernel<<<CONV_BLOCKS, 256>>>(x, c * KCH);
        }
        for (int c = 0; c < NCHUNK; c++)
            gemm_hmma_kernel<<<gemm_grid, 256>>>(out, c * KCH, c > 0 ? 1 : 0);
    }
}